// round 9
// baseline (speedup 1.0000x reference)
#include <cuda_runtime.h>
#include <cuda_bf16.h>
#include <cstdint>

#define BATCH 256
#define OUTF  1024
#define INF   1024

// ---------------- device scratch (no allocs allowed) ----------------
__device__ int g_flag = 0;   // monotonic: 0 = fast path valid
__device__ __nv_bfloat16 g_phi_hi[BATCH * INF];
__device__ __nv_bfloat16 g_phi_lo[BATCH * INF];
__device__ __nv_bfloat16 g_w_hi[OUTF * INF];
__device__ __nv_bfloat16 g_w_lo[OUTF * INF];

// ---------------- helpers ----------------
__device__ __forceinline__ uint32_t smem_u32(const void* p) {
    uint32_t a;
    asm("{ .reg .u64 t; cvta.to.shared.u64 t, %1; cvt.u32.u64 %0, t; }"
        : "=r"(a) : "l"(p));
    return a;
}

__device__ __forceinline__ void cp_async16(uint32_t dst, const void* src) {
    asm volatile("cp.async.cg.shared.global [%0], [%1], 16;"
                 :: "r"(dst), "l"(src) : "memory");
}
#define CP_COMMIT() asm volatile("cp.async.commit_group;" ::: "memory")
#define CP_WAIT(n)  asm volatile("cp.async.wait_group %0;" :: "n"(n) : "memory")

__device__ __forceinline__ void ldm_x4(uint32_t& r0, uint32_t& r1,
                                       uint32_t& r2, uint32_t& r3,
                                       uint32_t addr) {
    asm volatile("ldmatrix.sync.aligned.m8n8.x4.shared.b16 {%0,%1,%2,%3}, [%4];"
                 : "=r"(r0), "=r"(r1), "=r"(r2), "=r"(r3) : "r"(addr));
}

__device__ __forceinline__ void mma16816(float* c, const uint32_t* a,
                                         const uint32_t* b) {
    asm volatile(
        "mma.sync.aligned.m16n8k16.row.col.f32.bf16.bf16.f32 "
        "{%0,%1,%2,%3}, {%4,%5,%6,%7}, {%8,%9}, {%0,%1,%2,%3};"
        : "+f"(c[0]), "+f"(c[1]), "+f"(c[2]), "+f"(c[3])
        : "r"(a[0]), "r"(a[1]), "r"(a[2]), "r"(a[3]), "r"(b[0]), "r"(b[1]));
}

// pack 8 floats -> uint4 of bf16 (hi) and uint4 of residual (lo)
__device__ __forceinline__ void split8(const float4& a, const float4& b,
                                       uint4& hi, uint4& lo) {
    __nv_bfloat162 h0 = __floats2bfloat162_rn(a.x, a.y);
    __nv_bfloat162 h1 = __floats2bfloat162_rn(a.z, a.w);
    __nv_bfloat162 h2 = __floats2bfloat162_rn(b.x, b.y);
    __nv_bfloat162 h3 = __floats2bfloat162_rn(b.z, b.w);
    __nv_bfloat162 l0 = __floats2bfloat162_rn(a.x - __bfloat162float(h0.x),
                                              a.y - __bfloat162float(h0.y));
    __nv_bfloat162 l1 = __floats2bfloat162_rn(a.z - __bfloat162float(h1.x),
                                              a.w - __bfloat162float(h1.y));
    __nv_bfloat162 l2 = __floats2bfloat162_rn(b.x - __bfloat162float(h2.x),
                                              b.y - __bfloat162float(h2.y));
    __nv_bfloat162 l3 = __floats2bfloat162_rn(b.z - __bfloat162float(h3.x),
                                              b.w - __bfloat162float(h3.y));
    hi = make_uint4(*(uint32_t*)&h0, *(uint32_t*)&h1,
                    *(uint32_t*)&h2, *(uint32_t*)&h3);
    lo = make_uint4(*(uint32_t*)&l0, *(uint32_t*)&l1,
                    *(uint32_t*)&l2, *(uint32_t*)&l3);
}

__device__ __forceinline__ float dog(float x, float t, float s) {
    float z = (x - t) / s;
    return -z * __expf(-0.5f * z * z);
}

// ---------------- fused prep: check + W split + phi split ----------------
#define W_BLOCKS   ((OUTF * INF / 8) / 256)    // 512
#define PHI_BLOCKS ((BATCH * INF / 8) / 256)   // 128

__global__ __launch_bounds__(256)
void prep_kernel(const float4* __restrict__ w,
                 const float4* __restrict__ x,
                 const float4* __restrict__ scale,
                 const float4* __restrict__ trans) {
    if (blockIdx.x < W_BLOCKS) {
        int j = (blockIdx.x * 256 + threadIdx.x) * 2;
        int i40 = j & (INF / 4 - 1);
        int i41 = (j + 1) & (INF / 4 - 1);

        float4 w0 = w[j],     w1 = w[j + 1];
        float4 s0 = scale[j], s1 = scale[j + 1];
        float4 t0 = trans[j], t1 = trans[j + 1];
        float4 rs0 = scale[i40], rs1 = scale[i41];
        float4 rt0 = trans[i40], rt1 = trans[i41];

        bool bad =
            (s0.x != rs0.x) | (s0.y != rs0.y) | (s0.z != rs0.z) | (s0.w != rs0.w) |
            (s1.x != rs1.x) | (s1.y != rs1.y) | (s1.z != rs1.z) | (s1.w != rs1.w) |
            (t0.x != rt0.x) | (t0.y != rt0.y) | (t0.z != rt0.z) | (t0.w != rt0.w) |
            (t1.x != rt1.x) | (t1.y != rt1.y) | (t1.z != rt1.z) | (t1.w != rt1.w);
        if (bad) atomicOr(&g_flag, 1);

        uint4 hi, lo;
        split8(w0, w1, hi, lo);
        reinterpret_cast<uint4*>(g_w_hi)[j >> 1] = hi;
        reinterpret_cast<uint4*>(g_w_lo)[j >> 1] = lo;
    } else {
        int j = ((blockIdx.x - W_BLOCKS) * 256 + threadIdx.x) * 2;
        int i40 = j & (INF / 4 - 1);
        int i41 = (j + 1) & (INF / 4 - 1);
        float4 x0 = x[j], x1 = x[j + 1];
        float4 s0 = scale[i40], s1 = scale[i41];
        float4 t0 = trans[i40], t1 = trans[i41];
        float4 p0, p1;
        p0.x = dog(x0.x, t0.x, s0.x);
        p0.y = dog(x0.y, t0.y, s0.y);
        p0.z = dog(x0.z, t0.z, s0.z);
        p0.w = dog(x0.w, t0.w, s0.w);
        p1.x = dog(x1.x, t1.x, s1.x);
        p1.y = dog(x1.y, t1.y, s1.y);
        p1.z = dog(x1.z, t1.z, s1.z);
        p1.w = dog(x1.w, t1.w, s1.w);
        uint4 hi, lo;
        split8(p0, p1, hi, lo);
        reinterpret_cast<uint4*>(g_phi_hi)[j >> 1] = hi;
        reinterpret_cast<uint4*>(g_phi_lo)[j >> 1] = lo;
    }
}

// ---------------- split-bf16 mma.sync GEMM (+ exact fallback branch) ----
// CTA tile 32x32, 256 threads (8 warps, 2m x 4n), warp tile 16x8.
// BK=64, 3-stage cp.async pipeline. 3 independent acc chains per warp.
#define BM 32
#define BN 32
#define BK 64
#define NCHUNK (INF / BK)           // 16
#define ROWB    144                 // 72 bf16 per row (pad 8)
#define A_TILE  (BM * ROWB)         // 4608
#define B_TILE  (BN * ROWB)         // 4608
#define STAGEB  (2 * A_TILE + 2 * B_TILE)   // 18432
#define NSTAGE  3
#define GEMM_SMEM (NSTAGE * STAGEB)         // 55296

__global__ __launch_bounds__(256, 2)
void mma_gemm_kernel(float* __restrict__ out,
                     const float* __restrict__ x,
                     const float* __restrict__ w,
                     const float* __restrict__ s,
                     const float* __restrict__ t) {
    const int tid = threadIdx.x;
    const int m0 = blockIdx.y * BM;
    const int n0 = blockIdx.x * BN;

    if (g_flag) {
        // exact general path: 4 outputs per thread
        for (int e = tid; e < BM * BN; e += 256) {
            int b = m0 + (e >> 5);
            int o = n0 + (e & 31);
            const float* xr = x + (size_t)b * INF;
            const float* wr = w + (size_t)o * INF;
            const float* sr = s + (size_t)o * INF;
            const float* tr = t + (size_t)o * INF;
            float sum = 0.f;
            for (int i = 0; i < INF; ++i) {
                float z = (xr[i] - tr[i]) / sr[i];
                sum += wr[i] * (-z * __expf(-0.5f * z * z));
            }
            out[(size_t)b * OUTF + o] = sum;
        }
        return;
    }

    extern __shared__ char dsm[];
    const uint32_t sb = smem_u32(dsm);

    const int wid = tid >> 5, lid = tid & 31;
    const int wm = wid >> 2, wn = wid & 3;        // 2m x 4n warps, tile 16x8

    const __nv_bfloat16* gAh = g_phi_hi;
    const __nv_bfloat16* gAl = g_phi_lo;
    const __nv_bfloat16* gBh = g_w_hi;
    const __nv_bfloat16* gBl = g_w_lo;

    // 1024 cp.async of 16B per chunk, 4 per thread
    auto load_chunk = [&](int ci, int stage) {
        const int kc = ci * BK;
        const uint32_t st = sb + stage * STAGEB;
        #pragma unroll
        for (int it = 0; it < 4; it++) {
            int idx = tid + it * 256;
            if (idx < 512) {
                int tile = idx >> 8;            // 0=hi 1=lo
                int r = (idx >> 3) & 31;
                int q = idx & 7;
                const __nv_bfloat16* g = (tile ? gAl : gAh) +
                                         (size_t)(m0 + r) * INF + kc + q * 8;
                cp_async16(st + tile * A_TILE + r * ROWB + q * 16, g);
            } else {
                int idx2 = idx - 512;
                int tile = idx2 >> 8;
                int r = (idx2 >> 3) & 31;
                int q = idx2 & 7;
                const __nv_bfloat16* g = (tile ? gBl : gBh) +
                                         (size_t)(n0 + r) * INF + kc + q * 8;
                cp_async16(st + 2 * A_TILE + tile * B_TILE + r * ROWB + q * 16, g);
            }
        }
        CP_COMMIT();
    };

    float acc0[4] = {}, acc1[4] = {}, acc2[4] = {};

    load_chunk(0, 0);
    load_chunk(1, 1);

    // A frag addr: 16x16, B frag addr: 8 n-rows x k32 via ldm_x4
    const int a_row = wm * 16 + (lid & 15);
    const int a_colq = (lid >> 4) * 8;
    const int b_row = wn * 8 + (lid & 7);
    const int b_colq = (lid >> 3) * 8;          // 0,8,16,24 over k32

    for (int ci = 0; ci < NCHUNK; ci++) {
        if (ci + 2 < NCHUNK) load_chunk(ci + 2, (ci + 2) % NSTAGE);
        if (ci + 2 < NCHUNK)      { CP_WAIT(2); }
        else if (ci + 1 < NCHUNK) { CP_WAIT(1); }
        else                      { CP_WAIT(0); }
        __syncthreads();

        const uint32_t st = sb + (ci % NSTAGE) * STAGEB;
        const uint32_t sAh = st;
        const uint32_t sAl = st + A_TILE;
        const uint32_t sBh = st + 2 * A_TILE;
        const uint32_t sBl = st + 2 * A_TILE + B_TILE;

        #pragma unroll
        for (int kh = 0; kh < 2; kh++) {        // two k32 halves
            const int kb32 = kh * 32;
            uint32_t bh[4], bl[4];
            ldm_x4(bh[0], bh[1], bh[2], bh[3],
                   sBh + b_row * ROWB + (kb32 + b_colq) * 2);
            ldm_x4(bl[0], bl[1], bl[2], bl[3],
                   sBl + b_row * ROWB + (kb32 + b_colq) * 2);
            #pragma unroll
            for (int ks = 0; ks < 2; ks++) {    // k16 steps within k32
                const int kb = kb32 + ks * 16;
                uint32_t ah[4], al[4];
                ldm_x4(ah[0], ah[1], ah[2], ah[3],
                       sAh + a_row * ROWB + (kb + a_colq) * 2);
                ldm_x4(al[0], al[1], al[2], al[3],
                       sAl + a_row * ROWB + (kb + a_colq) * 2);
                mma16816(acc0, ah, &bh[ks * 2]);
                mma16816(acc1, ah, &bl[ks * 2]);
                mma16816(acc2, al, &bh[ks * 2]);
            }
        }
        __syncthreads();
    }

    const int row0 = m0 + wm * 16 + (lid >> 2);
    const int col = n0 + wn * 8 + (lid & 3) * 2;
    float c0 = acc0[0] + acc1[0] + acc2[0];
    float c1 = acc0[1] + acc1[1] + acc2[1];
    float c2 = acc0[2] + acc1[2] + acc2[2];
    float c3 = acc0[3] + acc1[3] + acc2[3];
    *reinterpret_cast<float2*>(&out[(size_t)row0 * OUTF + col]) =
        make_float2(c0, c1);
    *reinterpret_cast<float2*>(&out[(size_t)(row0 + 8) * OUTF + col]) =
        make_float2(c2, c3);
}

extern "C" void kernel_launch(void* const* d_in, const int* in_sizes, int n_in,
                              void* d_out, int out_size) {
    const float* x     = (const float*)d_in[0];
    const float* wgt   = (const float*)d_in[1];
    const float* scale = (const float*)d_in[2];
    const float* trans = (const float*)d_in[3];
    float* out = (float*)d_out;

    static bool attr_set = false;
    if (!attr_set) {
        cudaFuncSetAttribute(mma_gemm_kernel,
                             cudaFuncAttributeMaxDynamicSharedMemorySize,
                             GEMM_SMEM);
        attr_set = true;
    }

    prep_kernel<<<W_BLOCKS + PHI_BLOCKS, 256>>>(
        (const float4*)wgt, (const float4*)x,
        (const float4*)scale, (const float4*)trans);
    mma_gemm_kernel<<<dim3(OUTF / BN, BATCH / BM), 256, GEMM_SMEM>>>(
        out, x, wgt, scale, trans);
}

// round 10
// speedup vs baseline: 1.1050x; 1.1050x over previous
#include <cuda_runtime.h>
#include <cuda_bf16.h>
#include <cstdint>

#define BATCH 256
#define OUTF  1024
#define INF   1024

// ---------------- device scratch (no allocs allowed) ----------------
__device__ int g_flag = 0;   // monotonic: 0 = fast path valid
__device__ __nv_bfloat16 g_phi_hi[BATCH * INF];
__device__ __nv_bfloat16 g_phi_lo[BATCH * INF];
__device__ __nv_bfloat16 g_w_hi[OUTF * INF];
__device__ __nv_bfloat16 g_w_lo[OUTF * INF];

// ---------------- helpers ----------------
__device__ __forceinline__ uint32_t smem_u32(const void* p) {
    uint32_t a;
    asm("{ .reg .u64 t; cvta.to.shared.u64 t, %1; cvt.u32.u64 %0, t; }"
        : "=r"(a) : "l"(p));
    return a;
}

__device__ __forceinline__ void cp_async16(uint32_t dst, const void* src) {
    asm volatile("cp.async.cg.shared.global [%0], [%1], 16;"
                 :: "r"(dst), "l"(src) : "memory");
}
#define CP_COMMIT() asm volatile("cp.async.commit_group;" ::: "memory")
#define CP_WAIT(n)  asm volatile("cp.async.wait_group %0;" :: "n"(n) : "memory")

__device__ __forceinline__ void ldm_x4(uint32_t& r0, uint32_t& r1,
                                       uint32_t& r2, uint32_t& r3,
                                       uint32_t addr) {
    asm volatile("ldmatrix.sync.aligned.m8n8.x4.shared.b16 {%0,%1,%2,%3}, [%4];"
                 : "=r"(r0), "=r"(r1), "=r"(r2), "=r"(r3) : "r"(addr));
}

__device__ __forceinline__ void mma16816(float* c, const uint32_t* a,
                                         const uint32_t* b) {
    asm volatile(
        "mma.sync.aligned.m16n8k16.row.col.f32.bf16.bf16.f32 "
        "{%0,%1,%2,%3}, {%4,%5,%6,%7}, {%8,%9}, {%0,%1,%2,%3};"
        : "+f"(c[0]), "+f"(c[1]), "+f"(c[2]), "+f"(c[3])
        : "r"(a[0]), "r"(a[1]), "r"(a[2]), "r"(a[3]), "r"(b[0]), "r"(b[1]));
}

// pack 8 floats -> uint4 of bf16 (hi) and uint4 of residual (lo)
__device__ __forceinline__ void split8(const float4& a, const float4& b,
                                       uint4& hi, uint4& lo) {
    __nv_bfloat162 h0 = __floats2bfloat162_rn(a.x, a.y);
    __nv_bfloat162 h1 = __floats2bfloat162_rn(a.z, a.w);
    __nv_bfloat162 h2 = __floats2bfloat162_rn(b.x, b.y);
    __nv_bfloat162 h3 = __floats2bfloat162_rn(b.z, b.w);
    __nv_bfloat162 l0 = __floats2bfloat162_rn(a.x - __bfloat162float(h0.x),
                                              a.y - __bfloat162float(h0.y));
    __nv_bfloat162 l1 = __floats2bfloat162_rn(a.z - __bfloat162float(h1.x),
                                              a.w - __bfloat162float(h1.y));
    __nv_bfloat162 l2 = __floats2bfloat162_rn(b.x - __bfloat162float(h2.x),
                                              b.y - __bfloat162float(h2.y));
    __nv_bfloat162 l3 = __floats2bfloat162_rn(b.z - __bfloat162float(h3.x),
                                              b.w - __bfloat162float(h3.y));
    hi = make_uint4(*(uint32_t*)&h0, *(uint32_t*)&h1,
                    *(uint32_t*)&h2, *(uint32_t*)&h3);
    lo = make_uint4(*(uint32_t*)&l0, *(uint32_t*)&l1,
                    *(uint32_t*)&l2, *(uint32_t*)&l3);
}

__device__ __forceinline__ float dog(float x, float t, float s) {
    float z = (x - t) / s;
    return -z * __expf(-0.5f * z * z);
}

// ---------------- fused prep: check + W split + phi split ----------------
#define W_BLOCKS   ((OUTF * INF / 8) / 256)    // 512
#define PHI_BLOCKS ((BATCH * INF / 8) / 256)   // 128

__global__ __launch_bounds__(256)
void prep_kernel(const float4* __restrict__ w,
                 const float4* __restrict__ x,
                 const float4* __restrict__ scale,
                 const float4* __restrict__ trans) {
    if (blockIdx.x < W_BLOCKS) {
        int j = (blockIdx.x * 256 + threadIdx.x) * 2;
        int i40 = j & (INF / 4 - 1);
        int i41 = (j + 1) & (INF / 4 - 1);

        float4 w0 = w[j],     w1 = w[j + 1];
        float4 s0 = scale[j], s1 = scale[j + 1];
        float4 t0 = trans[j], t1 = trans[j + 1];
        float4 rs0 = scale[i40], rs1 = scale[i41];
        float4 rt0 = trans[i40], rt1 = trans[i41];

        bool bad =
            (s0.x != rs0.x) | (s0.y != rs0.y) | (s0.z != rs0.z) | (s0.w != rs0.w) |
            (s1.x != rs1.x) | (s1.y != rs1.y) | (s1.z != rs1.z) | (s1.w != rs1.w) |
            (t0.x != rt0.x) | (t0.y != rt0.y) | (t0.z != rt0.z) | (t0.w != rt0.w) |
            (t1.x != rt1.x) | (t1.y != rt1.y) | (t1.z != rt1.z) | (t1.w != rt1.w);
        if (bad) atomicOr(&g_flag, 1);

        uint4 hi, lo;
        split8(w0, w1, hi, lo);
        reinterpret_cast<uint4*>(g_w_hi)[j >> 1] = hi;
        reinterpret_cast<uint4*>(g_w_lo)[j >> 1] = lo;
    } else {
        int j = ((blockIdx.x - W_BLOCKS) * 256 + threadIdx.x) * 2;
        int i40 = j & (INF / 4 - 1);
        int i41 = (j + 1) & (INF / 4 - 1);
        float4 x0 = x[j], x1 = x[j + 1];
        float4 s0 = scale[i40], s1 = scale[i41];
        float4 t0 = trans[i40], t1 = trans[i41];
        float4 p0, p1;
        p0.x = dog(x0.x, t0.x, s0.x);
        p0.y = dog(x0.y, t0.y, s0.y);
        p0.z = dog(x0.z, t0.z, s0.z);
        p0.w = dog(x0.w, t0.w, s0.w);
        p1.x = dog(x1.x, t1.x, s1.x);
        p1.y = dog(x1.y, t1.y, s1.y);
        p1.z = dog(x1.z, t1.z, s1.z);
        p1.w = dog(x1.w, t1.w, s1.w);
        uint4 hi, lo;
        split8(p0, p1, hi, lo);
        reinterpret_cast<uint4*>(g_phi_hi)[j >> 1] = hi;
        reinterpret_cast<uint4*>(g_phi_lo)[j >> 1] = lo;
    }
}

// ---------------- split-bf16 mma.sync GEMM (+ exact fallback branch) ----
// CTA tile 32x64, 256 threads (8 warps, 2m x 4n), warp tile 16x16.
// BK=128 -> 8 chunks, ONE __syncthreads per chunk, 3-stage cp.async.
#define BM 32
#define BN 64
#define BK 128
#define NCHUNK (INF / BK)            // 8
#define ROWB    272                  // 136 bf16 per row (128 + pad 8)
#define A_TILE  (BM * ROWB)          // 8704
#define B_TILE  (BN * ROWB)          // 17408
#define STAGEB  (2 * A_TILE + 2 * B_TILE)   // 52224
#define NSTAGE  3
#define GEMM_SMEM (NSTAGE * STAGEB)         // 156672

__global__ __launch_bounds__(256, 1)
void mma_gemm_kernel(float* __restrict__ out,
                     const float* __restrict__ x,
                     const float* __restrict__ w,
                     const float* __restrict__ s,
                     const float* __restrict__ t) {
    const int tid = threadIdx.x;
    const int m0 = blockIdx.y * BM;
    const int n0 = blockIdx.x * BN;

    if (g_flag) {
        // exact general path: 8 outputs per thread
        for (int e = tid; e < BM * BN; e += 256) {
            int b = m0 + (e >> 6);
            int o = n0 + (e & 63);
            const float* xr = x + (size_t)b * INF;
            const float* wr = w + (size_t)o * INF;
            const float* sr = s + (size_t)o * INF;
            const float* tr = t + (size_t)o * INF;
            float sum = 0.f;
            for (int i = 0; i < INF; ++i) {
                float z = (xr[i] - tr[i]) / sr[i];
                sum += wr[i] * (-z * __expf(-0.5f * z * z));
            }
            out[(size_t)b * OUTF + o] = sum;
        }
        return;
    }

    extern __shared__ char dsm[];
    const uint32_t sb = smem_u32(dsm);

    const int wid = tid >> 5, lid = tid & 31;
    const int wm = wid >> 2, wn = wid & 3;        // 2m x 4n warps, tile 16x16

    const __nv_bfloat16* gAh = g_phi_hi;
    const __nv_bfloat16* gAl = g_phi_lo;
    const __nv_bfloat16* gBh = g_w_hi;
    const __nv_bfloat16* gBl = g_w_lo;

    // 3072 cp.async of 16B per chunk, 12 per thread
    auto load_chunk = [&](int ci, int stage) {
        const int kc = ci * BK;
        const uint32_t st = sb + stage * STAGEB;
        #pragma unroll
        for (int it = 0; it < 12; it++) {
            int idx = tid + it * 256;
            if (idx < 1024) {
                int tile = idx >> 9;             // 0=hi 1=lo
                int r = (idx >> 4) & 31;
                int q = idx & 15;
                const __nv_bfloat16* g = (tile ? gAl : gAh) +
                                         (size_t)(m0 + r) * INF + kc + q * 8;
                cp_async16(st + tile * A_TILE + r * ROWB + q * 16, g);
            } else {
                int idx2 = idx - 1024;
                int tile = idx2 >> 10;
                int r = (idx2 >> 4) & 63;
                int q = idx2 & 15;
                const __nv_bfloat16* g = (tile ? gBl : gBh) +
                                         (size_t)(n0 + r) * INF + kc + q * 8;
                cp_async16(st + 2 * A_TILE + tile * B_TILE + r * ROWB + q * 16, g);
            }
        }
        CP_COMMIT();
    };

    // 2 n-blocks x 3 split terms = 6 independent accumulator chains
    float acc0[2][4] = {{0}}, acc1[2][4] = {{0}}, acc2[2][4] = {{0}};

    load_chunk(0, 0);
    load_chunk(1, 1);

    const int a_row = wm * 16 + (lid & 15);
    const int a_colq = (lid >> 4) * 8;
    const int b_row7 = (lid & 7);
    const int b_colq = (lid >> 3) * 8;           // 0,8,16,24 over k32

    for (int ci = 0; ci < NCHUNK; ci++) {
        // drain through chunk ci (leave <=1 group = chunk ci+1 pending)
        if (ci + 1 < NCHUNK) { CP_WAIT(1); } else { CP_WAIT(0); }
        __syncthreads();   // publish chunk ci; retire stage (ci-1)%3

        if (ci + 2 < NCHUNK) load_chunk(ci + 2, (ci + 2) % NSTAGE);

        const uint32_t st = sb + (ci % NSTAGE) * STAGEB;
        const uint32_t sAh = st;
        const uint32_t sAl = st + A_TILE;
        const uint32_t sBh = st + 2 * A_TILE;
        const uint32_t sBl = st + 2 * A_TILE + B_TILE;

        #pragma unroll
        for (int kh = 0; kh < 4; kh++) {         // four k32 groups
            const int kb32 = kh * 32;
            uint32_t bh[2][4], bl[2][4];
            #pragma unroll
            for (int nb = 0; nb < 2; nb++) {
                const int brow = wn * 16 + nb * 8 + b_row7;
                ldm_x4(bh[nb][0], bh[nb][1], bh[nb][2], bh[nb][3],
                       sBh + brow * ROWB + (kb32 + b_colq) * 2);
                ldm_x4(bl[nb][0], bl[nb][1], bl[nb][2], bl[nb][3],
                       sBl + brow * ROWB + (kb32 + b_colq) * 2);
            }
            #pragma unroll
            for (int ks = 0; ks < 2; ks++) {     // k16 steps within k32
                const int kb = kb32 + ks * 16;
                uint32_t ah[4], al[4];
                ldm_x4(ah[0], ah[1], ah[2], ah[3],
                       sAh + a_row * ROWB + (kb + a_colq) * 2);
                ldm_x4(al[0], al[1], al[2], al[3],
                       sAl + a_row * ROWB + (kb + a_colq) * 2);
                #pragma unroll
                for (int nb = 0; nb < 2; nb++) {
                    mma16816(acc0[nb], ah, &bh[nb][ks * 2]);
                    mma16816(acc1[nb], ah, &bl[nb][ks * 2]);
                    mma16816(acc2[nb], al, &bh[nb][ks * 2]);
                }
            }
        }
    }

    const int row0 = m0 + wm * 16 + (lid >> 2);
    #pragma unroll
    for (int nb = 0; nb < 2; nb++) {
        const int col = n0 + wn * 16 + nb * 8 + (lid & 3) * 2;
        float c0 = acc0[nb][0] + acc1[nb][0] + acc2[nb][0];
        float c1 = acc0[nb][1] + acc1[nb][1] + acc2[nb][1];
        float c2 = acc0[nb][2] + acc1[nb][2] + acc2[nb][2];
        float c3 = acc0[nb][3] + acc1[nb][3] + acc2[nb][3];
        *reinterpret_cast<float2*>(&out[(size_t)row0 * OUTF + col]) =
            make_float2(c0, c1);
        *reinterpret_cast<float2*>(&out[(size_t)(row0 + 8) * OUTF + col]) =
            make_float2(c2, c3);
    }
}

extern "C" void kernel_launch(void* const* d_in, const int* in_sizes, int n_in,
                              void* d_out, int out_size) {
    const float* x     = (const float*)d_in[0];
    const float* wgt   = (const float*)d_in[1];
    const float* scale = (const float*)d_in[2];
    const float* trans = (const float*)d_in[3];
    float* out = (float*)d_out;

    static bool attr_set = false;
    if (!attr_set) {
        cudaFuncSetAttribute(mma_gemm_kernel,
                             cudaFuncAttributeMaxDynamicSharedMemorySize,
                             GEMM_SMEM);
        attr_set = true;
    }

    prep_kernel<<<W_BLOCKS + PHI_BLOCKS, 256>>>(
        (const float4*)wgt, (const float4*)x,
        (const float4*)scale, (const float4*)trans);
    mma_gemm_kernel<<<dim3(OUTF / BN, BATCH / BM), 256, GEMM_SMEM>>>(
        out, x, wgt, scale, trans);
}

// round 11
// speedup vs baseline: 1.6827x; 1.5228x over previous
#include <cuda_runtime.h>
#include <cuda_fp16.h>
#include <cstdint>

#define BATCH 256
#define OUTF  1024
#define INF   1024

// ---------------- device scratch (no allocs allowed) ----------------
__device__ int g_flag = 0;   // monotonic: 0 = fast path valid
__device__ __half g_phi_h[BATCH * INF];
__device__ __half g_w_h[OUTF * INF];

// ---------------- helpers ----------------
__device__ __forceinline__ uint32_t smem_u32(const void* p) {
    uint32_t a;
    asm("{ .reg .u64 t; cvta.to.shared.u64 t, %1; cvt.u32.u64 %0, t; }"
        : "=r"(a) : "l"(p));
    return a;
}

__device__ __forceinline__ void cp_async16(uint32_t dst, const void* src) {
    asm volatile("cp.async.cg.shared.global [%0], [%1], 16;"
                 :: "r"(dst), "l"(src) : "memory");
}
#define CP_COMMIT() asm volatile("cp.async.commit_group;" ::: "memory")
#define CP_WAIT(n)  asm volatile("cp.async.wait_group %0;" :: "n"(n) : "memory")

__device__ __forceinline__ void ldm_x4(uint32_t& r0, uint32_t& r1,
                                       uint32_t& r2, uint32_t& r3,
                                       uint32_t addr) {
    asm volatile("ldmatrix.sync.aligned.m8n8.x4.shared.b16 {%0,%1,%2,%3}, [%4];"
                 : "=r"(r0), "=r"(r1), "=r"(r2), "=r"(r3) : "r"(addr));
}

__device__ __forceinline__ void mma16816(float* c, const uint32_t* a,
                                         const uint32_t* b) {
    asm volatile(
        "mma.sync.aligned.m16n8k16.row.col.f32.f16.f16.f32 "
        "{%0,%1,%2,%3}, {%4,%5,%6,%7}, {%8,%9}, {%0,%1,%2,%3};"
        : "+f"(c[0]), "+f"(c[1]), "+f"(c[2]), "+f"(c[3])
        : "r"(a[0]), "r"(a[1]), "r"(a[2]), "r"(a[3]), "r"(b[0]), "r"(b[1]));
}

// pack 8 floats -> uint4 of fp16 (rn)
__device__ __forceinline__ uint4 pack8_h(const float4& a, const float4& b) {
    __half2 h0 = __floats2half2_rn(a.x, a.y);
    __half2 h1 = __floats2half2_rn(a.z, a.w);
    __half2 h2 = __floats2half2_rn(b.x, b.y);
    __half2 h3 = __floats2half2_rn(b.z, b.w);
    return make_uint4(*(uint32_t*)&h0, *(uint32_t*)&h1,
                      *(uint32_t*)&h2, *(uint32_t*)&h3);
}

__device__ __forceinline__ float dog(float x, float t, float s) {
    float z = (x - t) / s;
    return -z * __expf(-0.5f * z * z);
}

// ---------------- fused prep: check + W->fp16 + phi->fp16 ----------------
#define W_BLOCKS   ((OUTF * INF / 8) / 256)    // 512
#define PHI_BLOCKS ((BATCH * INF / 8) / 256)   // 128

__global__ __launch_bounds__(256)
void prep_kernel(const float4* __restrict__ w,
                 const float4* __restrict__ x,
                 const float4* __restrict__ scale,
                 const float4* __restrict__ trans) {
    if (blockIdx.x < W_BLOCKS) {
        int j = (blockIdx.x * 256 + threadIdx.x) * 2;
        int i40 = j & (INF / 4 - 1);
        int i41 = (j + 1) & (INF / 4 - 1);

        float4 w0 = w[j],     w1 = w[j + 1];
        float4 s0 = scale[j], s1 = scale[j + 1];
        float4 t0 = trans[j], t1 = trans[j + 1];
        float4 rs0 = scale[i40], rs1 = scale[i41];
        float4 rt0 = trans[i40], rt1 = trans[i41];

        bool bad =
            (s0.x != rs0.x) | (s0.y != rs0.y) | (s0.z != rs0.z) | (s0.w != rs0.w) |
            (s1.x != rs1.x) | (s1.y != rs1.y) | (s1.z != rs1.z) | (s1.w != rs1.w) |
            (t0.x != rt0.x) | (t0.y != rt0.y) | (t0.z != rt0.z) | (t0.w != rt0.w) |
            (t1.x != rt1.x) | (t1.y != rt1.y) | (t1.z != rt1.z) | (t1.w != rt1.w);
        if (bad) atomicOr(&g_flag, 1);

        reinterpret_cast<uint4*>(g_w_h)[j >> 1] = pack8_h(w0, w1);
    } else {
        int j = ((blockIdx.x - W_BLOCKS) * 256 + threadIdx.x) * 2;
        int i40 = j & (INF / 4 - 1);
        int i41 = (j + 1) & (INF / 4 - 1);
        float4 x0 = x[j], x1 = x[j + 1];
        float4 s0 = scale[i40], s1 = scale[i41];
        float4 t0 = trans[i40], t1 = trans[i41];
        float4 p0, p1;
        p0.x = dog(x0.x, t0.x, s0.x);
        p0.y = dog(x0.y, t0.y, s0.y);
        p0.z = dog(x0.z, t0.z, s0.z);
        p0.w = dog(x0.w, t0.w, s0.w);
        p1.x = dog(x1.x, t1.x, s1.x);
        p1.y = dog(x1.y, t1.y, s1.y);
        p1.z = dog(x1.z, t1.z, s1.z);
        p1.w = dog(x1.w, t1.w, s1.w);
        reinterpret_cast<uint4*>(g_phi_h)[j >> 1] = pack8_h(p0, p1);
    }
}

// ---------------- fp16 mma.sync GEMM (+ exact fallback branch) ----------
// out(256,1024) = phi @ W^T, single-pass fp16, f32 accumulate.
// CTA tile 32x64, 256 threads (8 warps, 2m x 4n), warp tile 16x16.
// BK=128 -> 8 chunks, one __syncthreads per chunk, 3-stage cp.async.
#define BM 32
#define BN 64
#define BK 128
#define NCHUNK (INF / BK)            // 8
#define ROWB    272                  // 128 fp16 = 256B + 16B pad
#define A_TILE  (BM * ROWB)          // 8704
#define B_TILE  (BN * ROWB)          // 17408
#define STAGEB  (A_TILE + B_TILE)    // 26112
#define NSTAGE  3
#define GEMM_SMEM (NSTAGE * STAGEB)  // 78336

__global__ __launch_bounds__(256, 1)
void mma_gemm_kernel(float* __restrict__ out,
                     const float* __restrict__ x,
                     const float* __restrict__ w,
                     const float* __restrict__ s,
                     const float* __restrict__ t) {
    const int tid = threadIdx.x;
    const int m0 = blockIdx.y * BM;
    const int n0 = blockIdx.x * BN;

    if (g_flag) {
        // exact general path: 8 outputs per thread
        for (int e = tid; e < BM * BN; e += 256) {
            int b = m0 + (e >> 6);
            int o = n0 + (e & 63);
            const float* xr = x + (size_t)b * INF;
            const float* wr = w + (size_t)o * INF;
            const float* sr = s + (size_t)o * INF;
            const float* tr = t + (size_t)o * INF;
            float sum = 0.f;
            for (int i = 0; i < INF; ++i) {
                float z = (xr[i] - tr[i]) / sr[i];
                sum += wr[i] * (-z * __expf(-0.5f * z * z));
            }
            out[(size_t)b * OUTF + o] = sum;
        }
        return;
    }

    extern __shared__ char dsm[];
    const uint32_t sb = smem_u32(dsm);

    const int wid = tid >> 5, lid = tid & 31;
    const int wm = wid >> 2, wn = wid & 3;        // 2m x 4n warps, tile 16x16

    // 1536 cp.async of 16B per chunk, 6 per thread
    auto load_chunk = [&](int ci, int stage) {
        const int kc = ci * BK;
        const uint32_t st = sb + stage * STAGEB;
        #pragma unroll
        for (int it = 0; it < 6; it++) {
            int idx = tid + it * 256;
            if (idx < 512) {
                int r = idx >> 4;                // 0..31
                int q = idx & 15;
                const __half* g = g_phi_h + (size_t)(m0 + r) * INF + kc + q * 8;
                cp_async16(st + r * ROWB + q * 16, g);
            } else {
                int idx2 = idx - 512;
                int r = idx2 >> 4;               // 0..63
                int q = idx2 & 15;
                const __half* g = g_w_h + (size_t)(n0 + r) * INF + kc + q * 8;
                cp_async16(st + A_TILE + r * ROWB + q * 16, g);
            }
        }
        CP_COMMIT();
    };

    float acc[2][4] = {{0}};

    load_chunk(0, 0);
    load_chunk(1, 1);

    const int a_row = wm * 16 + (lid & 15);
    const int a_colq = (lid >> 4) * 8;
    const int b_row7 = (lid & 7);
    const int b_colq = (lid >> 3) * 8;           // 0,8,16,24 over k32

    for (int ci = 0; ci < NCHUNK; ci++) {
        if (ci + 1 < NCHUNK) { CP_WAIT(1); } else { CP_WAIT(0); }
        __syncthreads();   // publish chunk ci; retire stage (ci-1)%3

        if (ci + 2 < NCHUNK) load_chunk(ci + 2, (ci + 2) % NSTAGE);

        const uint32_t sA = sb + (ci % NSTAGE) * STAGEB;
        const uint32_t sB = sA + A_TILE;

        #pragma unroll
        for (int kh = 0; kh < 4; kh++) {         // four k32 groups
            const int kb32 = kh * 32;
            uint32_t bfrag[2][4];
            #pragma unroll
            for (int nb = 0; nb < 2; nb++) {
                const int brow = wn * 16 + nb * 8 + b_row7;
                ldm_x4(bfrag[nb][0], bfrag[nb][1], bfrag[nb][2], bfrag[nb][3],
                       sB + brow * ROWB + (kb32 + b_colq) * 2);
            }
            #pragma unroll
            for (int ks = 0; ks < 2; ks++) {     // k16 steps within k32
                const int kb = kb32 + ks * 16;
                uint32_t afrag[4];
                ldm_x4(afrag[0], afrag[1], afrag[2], afrag[3],
                       sA + a_row * ROWB + (kb + a_colq) * 2);
                #pragma unroll
                for (int nb = 0; nb < 2; nb++)
                    mma16816(acc[nb], afrag, &bfrag[nb][ks * 2]);
            }
        }
    }

    const int row0 = m0 + wm * 16 + (lid >> 2);
    #pragma unroll
    for (int nb = 0; nb < 2; nb++) {
        const int col = n0 + wn * 16 + nb * 8 + (lid & 3) * 2;
        *reinterpret_cast<float2*>(&out[(size_t)row0 * OUTF + col]) =
            make_float2(acc[nb][0], acc[nb][1]);
        *reinterpret_cast<float2*>(&out[(size_t)(row0 + 8) * OUTF + col]) =
            make_float2(acc[nb][2], acc[nb][3]);
    }
}

extern "C" void kernel_launch(void* const* d_in, const int* in_sizes, int n_in,
                              void* d_out, int out_size) {
    const float* x     = (const float*)d_in[0];
    const float* wgt   = (const float*)d_in[1];
    const float* scale = (const float*)d_in[2];
    const float* trans = (const float*)d_in[3];
    float* out = (float*)d_out;

    static bool attr_set = false;
    if (!attr_set) {
        cudaFuncSetAttribute(mma_gemm_kernel,
                             cudaFuncAttributeMaxDynamicSharedMemorySize,
                             GEMM_SMEM);
        attr_set = true;
    }

    prep_kernel<<<W_BLOCKS + PHI_BLOCKS, 256>>>(
        (const float4*)wgt, (const float4*)x,
        (const float4*)scale, (const float4*)trans);
    mma_gemm_kernel<<<dim3(OUTF / BN, BATCH / BM), 256, GEMM_SMEM>>>(
        out, x, wgt, scale, trans);
}